// round 3
// baseline (speedup 1.0000x reference)
#include <cuda_runtime.h>
#include <cstdint>

#define BB 32
#define SS 127
#define HDIM 256
#define DD 64
#define M_ROWS (BB*SS)          // 4064 = 127 * 32
#define SCALE 0.125f

// -------- scratch (static device globals; allocation is forbidden) --------
__device__ float g_qp[M_ROWS*HDIM];
__device__ float g_kp[M_ROWS*HDIM];
__device__ float g_vp[M_ROWS*HDIM];
__device__ float g_x [M_ROWS*HDIM];

// float -> tf32 (round to nearest, keep in 32-bit reg for mma)
__device__ __forceinline__ uint32_t f2tf(float f) {
    uint32_t u;
    asm("cvt.rna.tf32.f32 %0, %1;" : "=r"(u) : "f"(f));
    return u;
}

// ---------------------------------------------------------------------------
// tf32 GEMM body: C[M,256] = A[M,256] @ W[256,256]^T + bias
// BM=32 (M=4064 = 127*32 exact), BN=64, 128 threads (4 warps, 2x2 warp grid,
// warp tile 16x32 via m16n8k8).
// ---------------------------------------------------------------------------
__device__ __forceinline__ void gemm_body(const float* __restrict__ A,
                                          const float* __restrict__ W,
                                          const float* __restrict__ bias,
                                          float* __restrict__ C)
{
    __shared__ uint32_t As[32][33];   // [m][k], pad
    __shared__ uint32_t Bs[32][65];   // [k][n], pad

    const int t     = threadIdx.x;
    const int lane  = t & 31;
    const int warp  = t >> 5;
    const int m0    = blockIdx.x * 32;
    const int n0    = blockIdx.y * 64;

    const int wm    = warp >> 1;      // 0..1
    const int wn    = warp & 1;       // 0..1
    const int mBase = wm * 16;
    const int nBase = wn * 32;
    const int gid   = lane >> 2;      // 0..7
    const int tig   = lane & 3;       // 0..3

    float acc[4][4];
    #pragma unroll
    for (int i = 0; i < 4; i++)
        #pragma unroll
        for (int j = 0; j < 4; j++) acc[i][j] = 0.0f;

    const int col   = t & 31;
    const int rbase = t >> 5;

    for (int k0 = 0; k0 < 256; k0 += 32) {
        // A tile: 32x32, coalesced rows
        #pragma unroll
        for (int i = 0; i < 8; i++) {
            int m = rbase + i * 4;
            As[m][col] = f2tf(A[(size_t)(m0 + m) * 256 + k0 + col]);
        }
        // W tile -> Bs[k][n] = W[n0+n][k0+k], coalesced along k
        #pragma unroll
        for (int i = 0; i < 16; i++) {
            int n = rbase + i * 4;
            Bs[col][n] = f2tf(W[(size_t)(n0 + n) * 256 + k0 + col]);
        }
        __syncthreads();

        #pragma unroll
        for (int s = 0; s < 4; s++) {
            uint32_t a0 = As[mBase + gid    ][s * 8 + tig    ];
            uint32_t a1 = As[mBase + gid + 8][s * 8 + tig    ];
            uint32_t a2 = As[mBase + gid    ][s * 8 + tig + 4];
            uint32_t a3 = As[mBase + gid + 8][s * 8 + tig + 4];
            #pragma unroll
            for (int nt = 0; nt < 4; nt++) {
                uint32_t b0 = Bs[s * 8 + tig    ][nBase + nt * 8 + gid];
                uint32_t b1 = Bs[s * 8 + tig + 4][nBase + nt * 8 + gid];
                asm volatile(
                    "mma.sync.aligned.m16n8k8.row.col.f32.tf32.tf32.f32 "
                    "{%0,%1,%2,%3}, {%4,%5,%6,%7}, {%8,%9}, {%0,%1,%2,%3};"
                    : "+f"(acc[nt][0]), "+f"(acc[nt][1]),
                      "+f"(acc[nt][2]), "+f"(acc[nt][3])
                    : "r"(a0), "r"(a1), "r"(a2), "r"(a3), "r"(b0), "r"(b1));
            }
        }
        __syncthreads();
    }

    #pragma unroll
    for (int nt = 0; nt < 4; nt++) {
        int c0 = n0 + nBase + nt * 8 + tig * 2;
        int r0 = m0 + mBase + gid;
        float bv0 = bias[c0], bv1 = bias[c0 + 1];
        C[(size_t)r0 * 256 + c0]           = acc[nt][0] + bv0;
        C[(size_t)r0 * 256 + c0 + 1]       = acc[nt][1] + bv1;
        C[(size_t)(r0 + 8) * 256 + c0]     = acc[nt][2] + bv0;
        C[(size_t)(r0 + 8) * 256 + c0 + 1] = acc[nt][3] + bv1;
    }
}

// QKV fused: blockIdx.z selects which projection
__global__ __launch_bounds__(128) void gemm_qkv_kernel(
    const float* __restrict__ q_in, const float* __restrict__ k_in,
    const float* __restrict__ v_in,
    const float* __restrict__ Wq, const float* __restrict__ Wk,
    const float* __restrict__ Wv,
    const float* __restrict__ bq, const float* __restrict__ bk,
    const float* __restrict__ bv)
{
    const float* A; const float* W; const float* bias; float* C;
    if (blockIdx.z == 0)      { A = q_in; W = Wq; bias = bq; C = g_qp; }
    else if (blockIdx.z == 1) { A = k_in; W = Wk; bias = bk; C = g_kp; }
    else                      { A = v_in; W = Wv; bias = bv; C = g_vp; }
    gemm_body(A, W, bias, C);
}

__global__ __launch_bounds__(128) void gemm_out_kernel(
    const float* __restrict__ Wo, const float* __restrict__ bo,
    float* __restrict__ out)
{
    gemm_body(g_x, Wo, bo, out);
}

// ---------------------------------------------------------------------------
// Attention: one block per (b,q). Exploits remove-mask sparsity:
// for q>=3 only k in {0,1,2,blk,blk+1} can be live. Masked columns contribute
// exactly 0 after softmax (exp(-1e5 - max) underflows in fp32) unless ALL
// columns are masked, in which case attn is uniform 1/S (fallback path).
// Score identity: score = (q_h + eq) . (k_h + ek) * SCALE  (4 einsums fused).
// ---------------------------------------------------------------------------
__global__ __launch_bounds__(128) void attn_kernel(
    const int*   __restrict__ graph,
    const float* __restrict__ e_key,
    const float* __restrict__ e_val,
    const float* __restrict__ e_qry)
{
    const int bid  = blockIdx.x;
    const int b    = bid / SS;
    const int q    = bid - b * SS;
    const int t    = threadIdx.x;
    const int lane = t & 31;
    const int w    = t >> 5;

    __shared__ float s_q[256];
    __shared__ int   s_list[128];
    __shared__ float s_sc[4][128];
    __shared__ int   s_wcnt[4];

    const int row = bid;                 // b*S + q
    s_q[t]       = g_qp[(size_t)row * 256 + t];
    s_q[t + 128] = g_qp[(size_t)row * 256 + 128 + t];

    // ---- build live-k list (ballot compaction) ----
    bool keep = false;
    const int k = t;
    if (k < SS) {
        bool rm;
        if (q < 3 || k < 3) rm = true;
        else {
            int blk = 3 + 2 * ((q - 3) >> 1);
            rm = (k >= blk) && (k < blk + 2);
        }
        if (rm) keep = (graph[((size_t)b * SS + q) * SS + k] != 0);
    }
    unsigned bal = __ballot_sync(0xFFFFFFFFu, keep);
    if (lane == 0) s_wcnt[w] = __popc(bal);
    __syncthreads();
    int base = 0;
    #pragma unroll
    for (int i = 0; i < 4; i++) base += (i < w) ? s_wcnt[i] : 0;
    const int total = s_wcnt[0] + s_wcnt[1] + s_wcnt[2] + s_wcnt[3];
    if (keep)
        s_list[base + __popc(bal & ((1u << lane) - 1))] = k;
    __syncthreads();

    // ---- scores: one warp per live k, all 4 heads at once ----
    for (int p = w; p < total; p += 4) {
        const int kk = s_list[p];
        const float* eqp = e_qry + ((size_t)(b * SS + kk) * SS + q) * DD;
        const float* ekp = e_key + ((size_t)(b * SS + q) * SS + kk) * DD;
        const float* kpp = g_kp + (size_t)(b * SS + kk) * 256;
        float eq0 = eqp[lane], eq1 = eqp[lane + 32];
        float ek0 = ekp[lane], ek1 = ekp[lane + 32];
        float ps[4];
        #pragma unroll
        for (int h = 0; h < 4; h++) {
            float qa = s_q[h * 64 + lane]      + eq0;
            float qb = s_q[h * 64 + lane + 32] + eq1;
            float ka = kpp[h * 64 + lane]      + ek0;
            float kb = kpp[h * 64 + lane + 32] + ek1;
            ps[h] = qa * ka + qb * kb;
        }
        #pragma unroll
        for (int off = 16; off; off >>= 1)
            #pragma unroll
            for (int h = 0; h < 4; h++)
                ps[h] += __shfl_down_sync(0xFFFFFFFFu, ps[h], off);
        if (lane == 0)
            #pragma unroll
            for (int h = 0; h < 4; h++) s_sc[h][p] = ps[h] * SCALE;
    }
    __syncthreads();

    // ---- softmax over live set (warp w == head h) ----
    if (w < 4 && total > 0) {
        float m = -3.0e38f;
        for (int p = lane; p < total; p += 32) m = fmaxf(m, s_sc[w][p]);
        #pragma unroll
        for (int off = 16; off; off >>= 1)
            m = fmaxf(m, __shfl_xor_sync(0xFFFFFFFFu, m, off));
        float sum = 0.0f;
        for (int p = lane; p < total; p += 32) {
            float e = __expf(s_sc[w][p] - m);
            s_sc[w][p] = e;
            sum += e;
        }
        #pragma unroll
        for (int off = 16; off; off >>= 1)
            sum += __shfl_xor_sync(0xFFFFFFFFu, sum, off);
        float inv = 1.0f / sum;
        for (int p = lane; p < total; p += 32) s_sc[w][p] *= inv;
    }
    __syncthreads();

    // ---- output: thread t owns (h0, d) and (h0+2, d) ----
    const int d  = t & 63;
    const int h0 = t >> 6;               // 0 or 1
    float acc0 = 0.0f, acc1 = 0.0f;
    const float* evbase = e_val + ((size_t)(b * SS + q) * SS) * DD;

    if (total > 0) {
        for (int p = 0; p < total; p++) {
            const int kk = s_list[p];
            float evv = evbase[(size_t)kk * DD + d];
            const float* vp = g_vp + (size_t)(b * SS + kk) * 256;
            acc0 += s_sc[h0][p]     * (vp[t]       + evv);
            acc1 += s_sc[h0 + 2][p] * (vp[t + 128] + evv);
        }
    } else {
        // all columns masked -> softmax of equal values -> uniform 1/S
        for (int kk = 0; kk < SS; kk++) {
            float evv = evbase[(size_t)kk * DD + d];
            const float* vp = g_vp + (size_t)(b * SS + kk) * 256;
            acc0 += vp[t]       + evv;
            acc1 += vp[t + 128] + evv;
        }
        const float invS = 1.0f / (float)SS;
        acc0 *= invS; acc1 *= invS;
    }
    g_x[(size_t)row * 256 + t]       = acc0;
    g_x[(size_t)row * 256 + 128 + t] = acc1;
}

// ---------------------------------------------------------------------------
extern "C" void kernel_launch(void* const* d_in, const int* in_sizes, int n_in,
                              void* d_out, int out_size)
{
    const float* query = (const float*)d_in[0];
    const float* key   = (const float*)d_in[1];
    const float* value = (const float*)d_in[2];
    const int*   graph = (const int*)  d_in[3];
    const float* e_key = (const float*)d_in[4];
    const float* e_val = (const float*)d_in[5];
    const float* e_qry = (const float*)d_in[6];
    const float* Wq = (const float*)d_in[7];
    const float* bq = (const float*)d_in[8];
    const float* Wk = (const float*)d_in[9];
    const float* bk = (const float*)d_in[10];
    const float* Wv = (const float*)d_in[11];
    const float* bv = (const float*)d_in[12];
    const float* Wo = (const float*)d_in[13];
    const float* bo = (const float*)d_in[14];
    float* out = (float*)d_out;

    dim3 g_qkv(M_ROWS / 32, 256 / 64, 3);
    gemm_qkv_kernel<<<g_qkv, 128>>>(query, key, value, Wq, Wk, Wv, bq, bk, bv);

    attn_kernel<<<M_ROWS, 128>>>(graph, e_key, e_val, e_qry);

    dim3 g_o(M_ROWS / 32, 256 / 64, 1);
    gemm_out_kernel<<<g_o, 128>>>(Wo, bo, out);
}

// round 6
// speedup vs baseline: 1.5323x; 1.5323x over previous
#include <cuda_runtime.h>
#include <cstdint>

#define BB 32
#define SS 127
#define HDIM 256
#define DD 64
#define M_ROWS (BB*SS)          // 4064 = 127 * 32
#define SCALE 0.125f

// -------- scratch (static device globals; allocation is forbidden) --------
__device__ float g_qp[M_ROWS*HDIM];
__device__ float g_kp[M_ROWS*HDIM];
__device__ float g_vp[M_ROWS*HDIM];
__device__ float g_x [M_ROWS*HDIM];

// float -> tf32 (round to nearest, keep in 32-bit reg for mma)
__device__ __forceinline__ uint32_t f2tf(float f) {
    uint32_t u;
    asm("cvt.rna.tf32.f32 %0, %1;" : "=r"(u) : "f"(f));
    return u;
}

// ---------------------------------------------------------------------------
// tf32 GEMM body: C[M,256] = A[M,256] @ W[256,256]^T + bias
// BM=32, BN=64, BK=32, 128 threads (4 warps, 2x2 warp grid, warp tile 16x32).
// Conflict-free operand loads: row stride 36 words => bank = gid*4 + tig
// (all 32 lanes distinct). Both As and Bs stored row-major [row][k].
// ---------------------------------------------------------------------------
__device__ __forceinline__ void gemm_body(const float* __restrict__ A,
                                          const float* __restrict__ W,
                                          const float* __restrict__ bias,
                                          float* __restrict__ C)
{
    __shared__ uint32_t As[32][36];   // [m][k], stride 36 => conflict-free frags
    __shared__ uint32_t Bs[64][36];   // [n][k], stride 36 => conflict-free frags

    const int t     = threadIdx.x;
    const int lane  = t & 31;
    const int warp  = t >> 5;
    const int m0    = blockIdx.x * 32;
    const int n0    = blockIdx.y * 64;

    const int wm    = warp >> 1;      // 0..1
    const int wn    = warp & 1;       // 0..1
    const int mBase = wm * 16;
    const int nBase = wn * 32;
    const int gid   = lane >> 2;      // 0..7
    const int tig   = lane & 3;       // 0..3

    float acc[4][4];
    #pragma unroll
    for (int i = 0; i < 4; i++)
        #pragma unroll
        for (int j = 0; j < 4; j++) acc[i][j] = 0.0f;

    const int lr  = t >> 3;           // 0..15 (tile-fill row)
    const int lc4 = (t & 7) * 4;      // 0,4,...,28 (tile-fill col*4)

    for (int k0 = 0; k0 < 256; k0 += 32) {
        // ---- A tile: 32 rows x 32 k, float4 loads ----
        {
            float4 v0 = *(const float4*)&A[(size_t)(m0 + lr) * 256 + k0 + lc4];
            float4 v1 = *(const float4*)&A[(size_t)(m0 + lr + 16) * 256 + k0 + lc4];
            As[lr][lc4]          = f2tf(v0.x); As[lr][lc4 + 1]      = f2tf(v0.y);
            As[lr][lc4 + 2]      = f2tf(v0.z); As[lr][lc4 + 3]      = f2tf(v0.w);
            As[lr + 16][lc4]     = f2tf(v1.x); As[lr + 16][lc4 + 1] = f2tf(v1.y);
            As[lr + 16][lc4 + 2] = f2tf(v1.z); As[lr + 16][lc4 + 3] = f2tf(v1.w);
        }
        // ---- B tile: 64 rows (n) x 32 k, row-major (same orientation as W) ----
        #pragma unroll
        for (int p = 0; p < 4; p++) {
            int n = lr + p * 16;
            float4 v = *(const float4*)&W[(size_t)(n0 + n) * 256 + k0 + lc4];
            Bs[n][lc4]     = f2tf(v.x); Bs[n][lc4 + 1] = f2tf(v.y);
            Bs[n][lc4 + 2] = f2tf(v.z); Bs[n][lc4 + 3] = f2tf(v.w);
        }
        __syncthreads();

        #pragma unroll
        for (int s = 0; s < 4; s++) {
            uint32_t a0 = As[mBase + gid    ][s * 8 + tig    ];
            uint32_t a1 = As[mBase + gid + 8][s * 8 + tig    ];
            uint32_t a2 = As[mBase + gid    ][s * 8 + tig + 4];
            uint32_t a3 = As[mBase + gid + 8][s * 8 + tig + 4];
            #pragma unroll
            for (int nt = 0; nt < 4; nt++) {
                uint32_t b0 = Bs[nBase + nt * 8 + gid][s * 8 + tig    ];
                uint32_t b1 = Bs[nBase + nt * 8 + gid][s * 8 + tig + 4];
                asm volatile(
                    "mma.sync.aligned.m16n8k8.row.col.f32.tf32.tf32.f32 "
                    "{%0,%1,%2,%3}, {%4,%5,%6,%7}, {%8,%9}, {%0,%1,%2,%3};"
                    : "+f"(acc[nt][0]), "+f"(acc[nt][1]),
                      "+f"(acc[nt][2]), "+f"(acc[nt][3])
                    : "r"(a0), "r"(a1), "r"(a2), "r"(a3), "r"(b0), "r"(b1));
            }
        }
        __syncthreads();
    }

    #pragma unroll
    for (int nt = 0; nt < 4; nt++) {
        int c0 = n0 + nBase + nt * 8 + tig * 2;
        int r0 = m0 + mBase + gid;
        float bv0 = bias[c0], bv1 = bias[c0 + 1];
        float2 o0 = make_float2(acc[nt][0] + bv0, acc[nt][1] + bv1);
        float2 o1 = make_float2(acc[nt][2] + bv0, acc[nt][3] + bv1);
        *(float2*)&C[(size_t)r0 * 256 + c0]       = o0;
        *(float2*)&C[(size_t)(r0 + 8) * 256 + c0] = o1;
    }
}

// QKV fused: blockIdx.z selects which projection
__global__ __launch_bounds__(128) void gemm_qkv_kernel(
    const float* __restrict__ q_in, const float* __restrict__ k_in,
    const float* __restrict__ v_in,
    const float* __restrict__ Wq, const float* __restrict__ Wk,
    const float* __restrict__ Wv,
    const float* __restrict__ bq, const float* __restrict__ bk,
    const float* __restrict__ bv)
{
    const float* A; const float* W; const float* bias; float* C;
    if (blockIdx.z == 0)      { A = q_in; W = Wq; bias = bq; C = g_qp; }
    else if (blockIdx.z == 1) { A = k_in; W = Wk; bias = bk; C = g_kp; }
    else                      { A = v_in; W = Wv; bias = bv; C = g_vp; }
    gemm_body(A, W, bias, C);
}

__global__ __launch_bounds__(128) void gemm_out_kernel(
    const float* __restrict__ Wo, const float* __restrict__ bo,
    float* __restrict__ out)
{
    gemm_body(g_x, Wo, bo, out);
}

// ---------------------------------------------------------------------------
// Attention: one block per (b,q). Exploits remove-mask sparsity:
// for q>=3 only k in {0,1,2,blk,blk+1} can be live. Masked columns contribute
// exactly 0 after softmax (exp(-1e5 - max) underflows in fp32) unless ALL
// columns are masked, in which case attn is uniform 1/S (fallback path).
// Score identity: score = (q_h + eq) . (k_h + ek) * SCALE  (4 einsums fused).
// ---------------------------------------------------------------------------
__global__ __launch_bounds__(128) void attn_kernel(
    const int*   __restrict__ graph,
    const float* __restrict__ e_key,
    const float* __restrict__ e_val,
    const float* __restrict__ e_qry)
{
    const int bid  = blockIdx.x;
    const int b    = bid / SS;
    const int q    = bid - b * SS;
    const int t    = threadIdx.x;
    const int lane = t & 31;
    const int w    = t >> 5;

    __shared__ float s_q[256];
    __shared__ int   s_list[128];
    __shared__ float s_sc[4][128];
    __shared__ int   s_wcnt[4];

    const int row = bid;                 // b*S + q
    s_q[t]       = g_qp[(size_t)row * 256 + t];
    s_q[t + 128] = g_qp[(size_t)row * 256 + 128 + t];

    // ---- build live-k list (ballot compaction) ----
    bool keep = false;
    const int k = t;
    if (k < SS) {
        bool rm;
        if (q < 3 || k < 3) rm = true;
        else {
            int blk = 3 + 2 * ((q - 3) >> 1);
            rm = (k >= blk) && (k < blk + 2);
        }
        if (rm) keep = (graph[((size_t)b * SS + q) * SS + k] != 0);
    }
    unsigned bal = __ballot_sync(0xFFFFFFFFu, keep);
    if (lane == 0) s_wcnt[w] = __popc(bal);
    __syncthreads();
    int base = 0;
    #pragma unroll
    for (int i = 0; i < 4; i++) base += (i < w) ? s_wcnt[i] : 0;
    const int total = s_wcnt[0] + s_wcnt[1] + s_wcnt[2] + s_wcnt[3];
    if (keep)
        s_list[base + __popc(bal & ((1u << lane) - 1))] = k;
    __syncthreads();

    // ---- scores: one warp per live k, all 4 heads at once ----
    for (int p = w; p < total; p += 4) {
        const int kk = s_list[p];
        const float* eqp = e_qry + ((size_t)(b * SS + kk) * SS + q) * DD;
        const float* ekp = e_key + ((size_t)(b * SS + q) * SS + kk) * DD;
        const float* kpp = g_kp + (size_t)(b * SS + kk) * 256;
        float eq0 = eqp[lane], eq1 = eqp[lane + 32];
        float ek0 = ekp[lane], ek1 = ekp[lane + 32];
        float ps[4];
        #pragma unroll
        for (int h = 0; h < 4; h++) {
            float qa = s_q[h * 64 + lane]      + eq0;
            float qb = s_q[h * 64 + lane + 32] + eq1;
            float ka = kpp[h * 64 + lane]      + ek0;
            float kb = kpp[h * 64 + lane + 32] + ek1;
            ps[h] = qa * ka + qb * kb;
        }
        #pragma unroll
        for (int off = 16; off; off >>= 1)
            #pragma unroll
            for (int h = 0; h < 4; h++)
                ps[h] += __shfl_down_sync(0xFFFFFFFFu, ps[h], off);
        if (lane == 0)
            #pragma unroll
            for (int h = 0; h < 4; h++) s_sc[h][p] = ps[h] * SCALE;
    }
    __syncthreads();

    // ---- softmax over live set (warp w == head h) ----
    if (total > 0) {
        float m = -3.0e38f;
        for (int p = lane; p < total; p += 32) m = fmaxf(m, s_sc[w][p]);
        #pragma unroll
        for (int off = 16; off; off >>= 1)
            m = fmaxf(m, __shfl_xor_sync(0xFFFFFFFFu, m, off));
        float sum = 0.0f;
        for (int p = lane; p < total; p += 32) {
            float e = __expf(s_sc[w][p] - m);
            s_sc[w][p] = e;
            sum += e;
        }
        #pragma unroll
        for (int off = 16; off; off >>= 1)
            sum += __shfl_xor_sync(0xFFFFFFFFu, sum, off);
        float inv = 1.0f / sum;
        for (int p = lane; p < total; p += 32) s_sc[w][p] *= inv;
    }
    __syncthreads();

    // ---- output: thread t owns (h0, d) and (h0+2, d) ----
    const int d  = t & 63;
    const int h0 = t >> 6;               // 0 or 1
    float acc0 = 0.0f, acc1 = 0.0f;
    const float* evbase = e_val + ((size_t)(b * SS + q) * SS) * DD;

    if (total > 0) {
        #pragma unroll 4
        for (int p = 0; p < total; p++) {
            const int kk = s_list[p];
            float evv = evbase[(size_t)kk * DD + d];
            const float* vp = g_vp + (size_t)(b * SS + kk) * 256;
            acc0 += s_sc[h0][p]     * (vp[t]       + evv);
            acc1 += s_sc[h0 + 2][p] * (vp[t + 128] + evv);
        }
    } else {
        // all columns masked -> softmax of equal values -> uniform 1/S
        #pragma unroll 4
        for (int kk = 0; kk < SS; kk++) {
            float evv = evbase[(size_t)kk * DD + d];
            const float* vp = g_vp + (size_t)(b * SS + kk) * 256;
            acc0 += vp[t]       + evv;
            acc1 += vp[t + 128] + evv;
        }
        const float invS = 1.0f / (float)SS;
        acc0 *= invS; acc1 *= invS;
    }
    g_x[(size_t)row * 256 + t]       = acc0;
    g_x[(size_t)row * 256 + 128 + t] = acc1;
}

// ---------------------------------------------------------------------------
extern "C" void kernel_launch(void* const* d_in, const int* in_sizes, int n_in,
                              void* d_out, int out_size)
{
    const float* query = (const float*)d_in[0];
    const float* key   = (const float*)d_in[1];
    const float* value = (const float*)d_in[2];
    const int*   graph = (const int*)  d_in[3];
    const float* e_key = (const float*)d_in[4];
    const float* e_val = (const float*)d_in[5];
    const float* e_qry = (const float*)d_in[6];
    const float* Wq = (const float*)d_in[7];
    const float* bq = (const float*)d_in[8];
    const float* Wk = (const float*)d_in[9];
    const float* bk = (const float*)d_in[10];
    const float* Wv = (const float*)d_in[11];
    const float* bv = (const float*)d_in[12];
    const float* Wo = (const float*)d_in[13];
    const float* bo = (const float*)d_in[14];
    float* out = (float*)d_out;

    dim3 g_qkv(M_ROWS / 32, 256 / 64, 3);
    gemm_qkv_kernel<<<g_qkv, 128>>>(query, key, value, Wq, Wk, Wv, bq, bk, bv);

    attn_kernel<<<M_ROWS, 128>>>(graph, e_key, e_val, e_qry);

    dim3 g_o(M_ROWS / 32, 256 / 64, 1);
    gemm_out_kernel<<<g_o, 128>>>(Wo, bo, out);
}

// round 9
// speedup vs baseline: 1.9146x; 1.2495x over previous
#include <cuda_runtime.h>
#include <cstdint>

#define BB 32
#define SS 127
#define HDIM 256
#define DD 64
#define M_ROWS (BB*SS)          // 4064 = 127 * 32
#define SCALE 0.125f

// -------- scratch (static device globals; allocation is forbidden) --------
__device__ float g_qp[M_ROWS*HDIM];
__device__ float g_kp[M_ROWS*HDIM];
__device__ float g_vp[M_ROWS*HDIM];
__device__ float g_x [M_ROWS*HDIM];

// float -> tf32 (round to nearest, keep in 32-bit reg for mma)
__device__ __forceinline__ uint32_t f2tf(float f) {
    uint32_t u;
    asm("cvt.rna.tf32.f32 %0, %1;" : "=r"(u) : "f"(f));
    return u;
}

// ---------------------------------------------------------------------------
// tf32 GEMM body v3: C[M,256] = A[M,256] @ W[256,256]^T + bias
// BM=32, BN=128, BK=64, 128 threads (4 warps, warp grid 1x4,
// warp tile 32x32 => mfrag=2 x nfrag=4: 2 LDS.32 per mma).
// Smem row stride 68 (= 4 mod 32): fragment bank = gid*4 + tig, conflict-free;
// fills are STS.128 (row*68 + 4c stays 16B aligned).
// ---------------------------------------------------------------------------
__device__ __forceinline__ void gemm_body(const float* __restrict__ A,
                                          const float* __restrict__ W,
                                          const float* __restrict__ bias,
                                          float* __restrict__ C)
{
    __shared__ uint32_t As[32][68];    // 8.5 KB
    __shared__ uint32_t Bs[128][68];   // 34 KB

    const int t     = threadIdx.x;
    const int lane  = t & 31;
    const int warp  = t >> 5;
    const int m0    = blockIdx.x * 32;
    const int n0    = blockIdx.y * 128;

    const int nBase = warp * 32;
    const int gid   = lane >> 2;      // 0..7
    const int tig   = lane & 3;       // 0..3

    float acc[2][4][4];
    #pragma unroll
    for (int mf = 0; mf < 2; mf++)
        #pragma unroll
        for (int nt = 0; nt < 4; nt++)
            #pragma unroll
            for (int r = 0; r < 4; r++) acc[mf][nt][r] = 0.0f;

    const int fr = t >> 4;            // 0..7  (fill row base)
    const int fc = (t & 15) * 4;      // 0..60 (fill col, float4 granularity)

    for (int k0 = 0; k0 < 256; k0 += 64) {
        // ---- A tile: 32 rows x 64 k ----
        #pragma unroll
        for (int i = 0; i < 4; i++) {
            float4 v = *(const float4*)&A[(size_t)(m0 + fr + i * 8) * 256 + k0 + fc];
            uint4 u = make_uint4(f2tf(v.x), f2tf(v.y), f2tf(v.z), f2tf(v.w));
            *(uint4*)&As[fr + i * 8][fc] = u;
        }
        // ---- B tile: 128 rows (n) x 64 k ----
        #pragma unroll
        for (int i = 0; i < 16; i++) {
            float4 v = *(const float4*)&W[(size_t)(n0 + fr + i * 8) * 256 + k0 + fc];
            uint4 u = make_uint4(f2tf(v.x), f2tf(v.y), f2tf(v.z), f2tf(v.w));
            *(uint4*)&Bs[fr + i * 8][fc] = u;
        }
        __syncthreads();

        #pragma unroll
        for (int s = 0; s < 8; s++) {
            uint32_t a[2][4];
            #pragma unroll
            for (int mf = 0; mf < 2; mf++) {
                a[mf][0] = As[mf * 16 + gid    ][s * 8 + tig    ];
                a[mf][1] = As[mf * 16 + gid + 8][s * 8 + tig    ];
                a[mf][2] = As[mf * 16 + gid    ][s * 8 + tig + 4];
                a[mf][3] = As[mf * 16 + gid + 8][s * 8 + tig + 4];
            }
            #pragma unroll
            for (int nt = 0; nt < 4; nt++) {
                uint32_t b0 = Bs[nBase + nt * 8 + gid][s * 8 + tig    ];
                uint32_t b1 = Bs[nBase + nt * 8 + gid][s * 8 + tig + 4];
                #pragma unroll
                for (int mf = 0; mf < 2; mf++) {
                    asm volatile(
                        "mma.sync.aligned.m16n8k8.row.col.f32.tf32.tf32.f32 "
                        "{%0,%1,%2,%3}, {%4,%5,%6,%7}, {%8,%9}, {%0,%1,%2,%3};"
                        : "+f"(acc[mf][nt][0]), "+f"(acc[mf][nt][1]),
                          "+f"(acc[mf][nt][2]), "+f"(acc[mf][nt][3])
                        : "r"(a[mf][0]), "r"(a[mf][1]), "r"(a[mf][2]), "r"(a[mf][3]),
                          "r"(b0), "r"(b1));
                }
            }
        }
        __syncthreads();
    }

    #pragma unroll
    for (int mf = 0; mf < 2; mf++)
        #pragma unroll
        for (int nt = 0; nt < 4; nt++) {
            int c0 = n0 + nBase + nt * 8 + tig * 2;
            int r0 = m0 + mf * 16 + gid;
            float bv0 = bias[c0], bv1 = bias[c0 + 1];
            float2 o0 = make_float2(acc[mf][nt][0] + bv0, acc[mf][nt][1] + bv1);
            float2 o1 = make_float2(acc[mf][nt][2] + bv0, acc[mf][nt][3] + bv1);
            *(float2*)&C[(size_t)r0 * 256 + c0]       = o0;
            *(float2*)&C[(size_t)(r0 + 8) * 256 + c0] = o1;
        }
}

// QKV fused: blockIdx.z selects which projection
__global__ __launch_bounds__(128) void gemm_qkv_kernel(
    const float* __restrict__ q_in, const float* __restrict__ k_in,
    const float* __restrict__ v_in,
    const float* __restrict__ Wq, const float* __restrict__ Wk,
    const float* __restrict__ Wv,
    const float* __restrict__ bq, const float* __restrict__ bk,
    const float* __restrict__ bv)
{
    const float* A; const float* W; const float* bias; float* C;
    if (blockIdx.z == 0)      { A = q_in; W = Wq; bias = bq; C = g_qp; }
    else if (blockIdx.z == 1) { A = k_in; W = Wk; bias = bk; C = g_kp; }
    else                      { A = v_in; W = Wv; bias = bv; C = g_vp; }
    gemm_body(A, W, bias, C);
}

__global__ __launch_bounds__(128) void gemm_out_kernel(
    const float* __restrict__ Wo, const float* __restrict__ bo,
    float* __restrict__ out)
{
    gemm_body(g_x, Wo, bo, out);
}

// ---------------------------------------------------------------------------
// Attention: one block per (b,q). Exploits remove-mask sparsity:
// for q>=3 only k in {0,1,2,blk,blk+1} can be live. Masked columns contribute
// exactly 0 after softmax (exp(-1e5 - max) underflows in fp32) unless ALL
// columns are masked, in which case attn is uniform 1/S (fallback path).
// Score identity: score = (q_h + eq) . (k_h + ek) * SCALE  (4 einsums fused).
// ---------------------------------------------------------------------------
__global__ __launch_bounds__(128) void attn_kernel(
    const int*   __restrict__ graph,
    const float* __restrict__ e_key,
    const float* __restrict__ e_val,
    const float* __restrict__ e_qry)
{
    const int bid  = blockIdx.x;
    const int b    = bid / SS;
    const int q    = bid - b * SS;
    const int t    = threadIdx.x;
    const int lane = t & 31;
    const int w    = t >> 5;

    __shared__ float s_q[256];
    __shared__ int   s_list[128];
    __shared__ float s_sc[4][128];
    __shared__ int   s_wcnt[4];

    const int row = bid;                 // b*S + q
    s_q[t]       = g_qp[(size_t)row * 256 + t];
    s_q[t + 128] = g_qp[(size_t)row * 256 + 128 + t];

    // ---- build live-k list (ballot compaction) ----
    bool keep = false;
    const int k = t;
    if (k < SS) {
        bool rm;
        if (q < 3 || k < 3) rm = true;
        else {
            int blk = 3 + 2 * ((q - 3) >> 1);
            rm = (k >= blk) && (k < blk + 2);
        }
        if (rm) keep = (graph[((size_t)b * SS + q) * SS + k] != 0);
    }
    unsigned bal = __ballot_sync(0xFFFFFFFFu, keep);
    if (lane == 0) s_wcnt[w] = __popc(bal);
    __syncthreads();
    int base = 0;
    #pragma unroll
    for (int i = 0; i < 4; i++) base += (i < w) ? s_wcnt[i] : 0;
    const int total = s_wcnt[0] + s_wcnt[1] + s_wcnt[2] + s_wcnt[3];
    if (keep)
        s_list[base + __popc(bal & ((1u << lane) - 1))] = k;
    __syncthreads();

    // ---- scores: one warp per live k, all 4 heads at once ----
    for (int p = w; p < total; p += 4) {
        const int kk = s_list[p];
        const float* eqp = e_qry + ((size_t)(b * SS + kk) * SS + q) * DD;
        const float* ekp = e_key + ((size_t)(b * SS + q) * SS + kk) * DD;
        const float* kpp = g_kp + (size_t)(b * SS + kk) * 256;
        float eq0 = eqp[lane], eq1 = eqp[lane + 32];
        float ek0 = ekp[lane], ek1 = ekp[lane + 32];
        float ps[4];
        #pragma unroll
        for (int h = 0; h < 4; h++) {
            float qa = s_q[h * 64 + lane]      + eq0;
            float qb = s_q[h * 64 + lane + 32] + eq1;
            float ka = kpp[h * 64 + lane]      + ek0;
            float kb = kpp[h * 64 + lane + 32] + ek1;
            ps[h] = qa * ka + qb * kb;
        }
        #pragma unroll
        for (int off = 16; off; off >>= 1)
            #pragma unroll
            for (int h = 0; h < 4; h++)
                ps[h] += __shfl_down_sync(0xFFFFFFFFu, ps[h], off);
        if (lane == 0)
            #pragma unroll
            for (int h = 0; h < 4; h++) s_sc[h][p] = ps[h] * SCALE;
    }
    __syncthreads();

    // ---- softmax over live set (warp w == head h) ----
    if (total > 0) {
        float m = -3.0e38f;
        for (int p = lane; p < total; p += 32) m = fmaxf(m, s_sc[w][p]);
        #pragma unroll
        for (int off = 16; off; off >>= 1)
            m = fmaxf(m, __shfl_xor_sync(0xFFFFFFFFu, m, off));
        float sum = 0.0f;
        for (int p = lane; p < total; p += 32) {
            float e = __expf(s_sc[w][p] - m);
            s_sc[w][p] = e;
            sum += e;
        }
        #pragma unroll
        for (int off = 16; off; off >>= 1)
            sum += __shfl_xor_sync(0xFFFFFFFFu, sum, off);
        float inv = 1.0f / sum;
        for (int p = lane; p < total; p += 32) s_sc[w][p] *= inv;
    }
    __syncthreads();

    // ---- output: thread t owns one float2 of the 256-wide row ----
    // element pair e = hp*128 + dp*2, e+1; head h = 2*hp + (dp>=32); d = (2dp)&63
    const int dp = t & 63;
    const int hp = t >> 6;               // 0 or 1
    const int h  = 2 * hp + (dp >> 5);
    const int dd = (dp * 2) & 63;
    float2 acc = make_float2(0.0f, 0.0f);
    const float* evbase = e_val + ((size_t)(b * SS + q) * SS) * DD;

    if (total > 0) {
        #pragma unroll 4
        for (int p = 0; p < total; p++) {
            const int kk = s_list[p];
            float2 ev = *(const float2*)&evbase[(size_t)kk * DD + dd];
            float2 vv = *(const float2*)&g_vp[(size_t)(b * SS + kk) * 256 + hp * 128 + dp * 2];
            float sc = s_sc[h][p];
            acc.x += sc * (vv.x + ev.x);
            acc.y += sc * (vv.y + ev.y);
        }
    } else {
        // all columns masked -> softmax of equal values -> uniform 1/S
        #pragma unroll 4
        for (int kk = 0; kk < SS; kk++) {
            float2 ev = *(const float2*)&evbase[(size_t)kk * DD + dd];
            float2 vv = *(const float2*)&g_vp[(size_t)(b * SS + kk) * 256 + hp * 128 + dp * 2];
            acc.x += vv.x + ev.x;
            acc.y += vv.y + ev.y;
        }
        const float invS = 1.0f / (float)SS;
        acc.x *= invS; acc.y *= invS;
    }
    *(float2*)&g_x[(size_t)row * 256 + hp * 128 + dp * 2] = acc;
}

// ---------------------------------------------------------------------------
extern "C" void kernel_launch(void* const* d_in, const int* in_sizes, int n_in,
                              void* d_out, int out_size)
{
    const float* query = (const float*)d_in[0];
    const float* key   = (const float*)d_in[1];
    const float* value = (const float*)d_in[2];
    const int*   graph = (const int*)  d_in[3];
    const float* e_key = (const float*)d_in[4];
    const float* e_val = (const float*)d_in[5];
    const float* e_qry = (const float*)d_in[6];
    const float* Wq = (const float*)d_in[7];
    const float* bq = (const float*)d_in[8];
    const float* Wk = (const float*)d_in[9];
    const float* bk = (const float*)d_in[10];
    const float* Wv = (const float*)d_in[11];
    const float* bv = (const float*)d_in[12];
    const float* Wo = (const float*)d_in[13];
    const float* bo = (const float*)d_in[14];
    float* out = (float*)d_out;

    dim3 g_qkv(M_ROWS / 32, 256 / 128, 3);
    gemm_qkv_kernel<<<g_qkv, 128>>>(query, key, value, Wq, Wk, Wv, bq, bk, bv);

    attn_kernel<<<M_ROWS, 128>>>(graph, e_key, e_val, e_qry);

    dim3 g_o(M_ROWS / 32, 256 / 128, 1);
    gemm_out_kernel<<<g_o, 128>>>(Wo, bo, out);
}

// round 10
// speedup vs baseline: 2.2944x; 1.1984x over previous
#include <cuda_runtime.h>
#include <cstdint>

#define BB 32
#define SS 127
#define HDIM 256
#define DD 64
#define M_ROWS (BB*SS)          // 4064 = 127 * 32
#define SCALE 0.125f

// -------- scratch (static device globals; allocation is forbidden) --------
__device__ float g_qp[M_ROWS*HDIM];
__device__ float g_kp[M_ROWS*HDIM];
__device__ float g_vp[M_ROWS*HDIM];
__device__ float g_x [M_ROWS*HDIM];

// float -> tf32 (round to nearest, keep in 32-bit reg for mma)
__device__ __forceinline__ uint32_t f2tf(float f) {
    uint32_t u;
    asm("cvt.rna.tf32.f32 %0, %1;" : "=r"(u) : "f"(f));
    return u;
}

__device__ __forceinline__ void cpasync16(uint32_t s_addr, const void* gptr) {
    asm volatile("cp.async.ca.shared.global [%0], [%1], 16;"
                 :: "r"(s_addr), "l"(gptr));
}
__device__ __forceinline__ void cpasync_commit() {
    asm volatile("cp.async.commit_group;");
}
template <int N>
__device__ __forceinline__ void cpasync_wait() {
    asm volatile("cp.async.wait_group %0;" :: "n"(N));
}

// ---------------------------------------------------------------------------
// tf32 GEMM body v4: C[M,256] = A[M,256] @ W[256,256]^T + bias
// BM=32, BN=128, BK=32, 128 threads (4 warps, warp grid 1x4, warp tile 32x32).
// Double-buffered cp.async fills (raw float); tf32 convert at fragment load.
// Smem row stride 36 (= 4 mod 32): fragment bank = gid*4 + tig, conflict-free.
// ---------------------------------------------------------------------------
__device__ __forceinline__ void gemm_body(const float* __restrict__ A,
                                          const float* __restrict__ W,
                                          const float* __restrict__ bias,
                                          float* __restrict__ C)
{
    __shared__ float As[2][32][36];    // 2 * 4.5 KB
    __shared__ float Bs[2][128][36];   // 2 * 18 KB   (total 45 KB)

    const int t     = threadIdx.x;
    const int lane  = t & 31;
    const int warp  = t >> 5;
    const int m0    = blockIdx.x * 32;
    const int n0    = blockIdx.y * 128;

    const int nBase = warp * 32;
    const int gid   = lane >> 2;      // 0..7
    const int tig   = lane & 3;       // 0..3

    float acc[2][4][4];
    #pragma unroll
    for (int mf = 0; mf < 2; mf++)
        #pragma unroll
        for (int nt = 0; nt < 4; nt++)
            #pragma unroll
            for (int r = 0; r < 4; r++) acc[mf][nt][r] = 0.0f;

    const int fr = t >> 3;            // 0..15 (fill row base)
    const int fc = (t & 7) * 4;       // 0..28 (fill col, float4 granularity)

    // prefetch helper: stage kt (k0 = kt*32) into buffer buf
    auto prefetch = [&](int kt, int buf) {
        const int k0 = kt * 32;
        #pragma unroll
        for (int i = 0; i < 2; i++) {
            uint32_t dst = (uint32_t)__cvta_generic_to_shared(&As[buf][fr + i * 16][fc]);
            cpasync16(dst, &A[(size_t)(m0 + fr + i * 16) * 256 + k0 + fc]);
        }
        #pragma unroll
        for (int i = 0; i < 8; i++) {
            uint32_t dst = (uint32_t)__cvta_generic_to_shared(&Bs[buf][fr + i * 16][fc]);
            cpasync16(dst, &W[(size_t)(n0 + fr + i * 16) * 256 + k0 + fc]);
        }
        cpasync_commit();
    };

    prefetch(0, 0);

    for (int kt = 0; kt < 8; kt++) {
        const int cur = kt & 1;
        if (kt + 1 < 8) {
            prefetch(kt + 1, cur ^ 1);
            cpasync_wait<1>();       // current stage complete; next in flight
        } else {
            cpasync_wait<0>();
        }
        __syncthreads();

        #pragma unroll
        for (int s = 0; s < 4; s++) {
            uint32_t a[2][4];
            #pragma unroll
            for (int mf = 0; mf < 2; mf++) {
                a[mf][0] = f2tf(As[cur][mf * 16 + gid    ][s * 8 + tig    ]);
                a[mf][1] = f2tf(As[cur][mf * 16 + gid + 8][s * 8 + tig    ]);
                a[mf][2] = f2tf(As[cur][mf * 16 + gid    ][s * 8 + tig + 4]);
                a[mf][3] = f2tf(As[cur][mf * 16 + gid + 8][s * 8 + tig + 4]);
            }
            #pragma unroll
            for (int nt = 0; nt < 4; nt++) {
                uint32_t b0 = f2tf(Bs[cur][nBase + nt * 8 + gid][s * 8 + tig    ]);
                uint32_t b1 = f2tf(Bs[cur][nBase + nt * 8 + gid][s * 8 + tig + 4]);
                #pragma unroll
                for (int mf = 0; mf < 2; mf++) {
                    asm volatile(
                        "mma.sync.aligned.m16n8k8.row.col.f32.tf32.tf32.f32 "
                        "{%0,%1,%2,%3}, {%4,%5,%6,%7}, {%8,%9}, {%0,%1,%2,%3};"
                        : "+f"(acc[mf][nt][0]), "+f"(acc[mf][nt][1]),
                          "+f"(acc[mf][nt][2]), "+f"(acc[mf][nt][3])
                        : "r"(a[mf][0]), "r"(a[mf][1]), "r"(a[mf][2]), "r"(a[mf][3]),
                          "r"(b0), "r"(b1));
                }
            }
        }
        __syncthreads();
    }

    #pragma unroll
    for (int mf = 0; mf < 2; mf++)
        #pragma unroll
        for (int nt = 0; nt < 4; nt++) {
            int c0 = n0 + nBase + nt * 8 + tig * 2;
            int r0 = m0 + mf * 16 + gid;
            float bv0 = bias[c0], bv1 = bias[c0 + 1];
            float2 o0 = make_float2(acc[mf][nt][0] + bv0, acc[mf][nt][1] + bv1);
            float2 o1 = make_float2(acc[mf][nt][2] + bv0, acc[mf][nt][3] + bv1);
            *(float2*)&C[(size_t)r0 * 256 + c0]       = o0;
            *(float2*)&C[(size_t)(r0 + 8) * 256 + c0] = o1;
        }
}

// QKV fused: blockIdx.z selects which projection
__global__ __launch_bounds__(128) void gemm_qkv_kernel(
    const float* __restrict__ q_in, const float* __restrict__ k_in,
    const float* __restrict__ v_in,
    const float* __restrict__ Wq, const float* __restrict__ Wk,
    const float* __restrict__ Wv,
    const float* __restrict__ bq, const float* __restrict__ bk,
    const float* __restrict__ bv)
{
    const float* A; const float* W; const float* bias; float* C;
    if (blockIdx.z == 0)      { A = q_in; W = Wq; bias = bq; C = g_qp; }
    else if (blockIdx.z == 1) { A = k_in; W = Wk; bias = bk; C = g_kp; }
    else                      { A = v_in; W = Wv; bias = bv; C = g_vp; }
    gemm_body(A, W, bias, C);
}

__global__ __launch_bounds__(128) void gemm_out_kernel(
    const float* __restrict__ Wo, const float* __restrict__ bo,
    float* __restrict__ out)
{
    gemm_body(g_x, Wo, bo, out);
}

// ---------------------------------------------------------------------------
// Attention: one block per (b,q). Exploits remove-mask sparsity:
// for q>=3 only k in {0,1,2,blk,blk+1} can be live. Masked columns contribute
// exactly 0 after softmax (exp(-1e5 - max) underflows in fp32) unless ALL
// columns are masked, in which case attn is uniform 1/S (fallback path).
// Score identity: score = (q_h + eq) . (k_h + ek) * SCALE  (4 einsums fused).
// ---------------------------------------------------------------------------
__global__ __launch_bounds__(128) void attn_kernel(
    const int*   __restrict__ graph,
    const float* __restrict__ e_key,
    const float* __restrict__ e_val,
    const float* __restrict__ e_qry)
{
    const int bid  = blockIdx.x;
    const int b    = bid / SS;
    const int q    = bid - b * SS;
    const int t    = threadIdx.x;
    const int lane = t & 31;
    const int w    = t >> 5;

    __shared__ float s_q[256];
    __shared__ int   s_list[128];
    __shared__ float s_sc[4][128];
    __shared__ int   s_wcnt[4];

    const int row = bid;                 // b*S + q
    s_q[t]       = g_qp[(size_t)row * 256 + t];
    s_q[t + 128] = g_qp[(size_t)row * 256 + 128 + t];

    // ---- build live-k list (ballot compaction) ----
    bool keep = false;
    const int k = t;
    if (k < SS) {
        bool rm;
        if (q < 3 || k < 3) rm = true;
        else {
            int blk = 3 + 2 * ((q - 3) >> 1);
            rm = (k >= blk) && (k < blk + 2);
        }
        if (rm) keep = (graph[((size_t)b * SS + q) * SS + k] != 0);
    }
    unsigned bal = __ballot_sync(0xFFFFFFFFu, keep);
    if (lane == 0) s_wcnt[w] = __popc(bal);
    __syncthreads();
    int base = 0;
    #pragma unroll
    for (int i = 0; i < 4; i++) base += (i < w) ? s_wcnt[i] : 0;
    const int total = s_wcnt[0] + s_wcnt[1] + s_wcnt[2] + s_wcnt[3];
    if (keep)
        s_list[base + __popc(bal & ((1u << lane) - 1))] = k;
    __syncthreads();

    // ---- scores: one warp per live k, all 4 heads at once (float2/lane) ----
    for (int p = w; p < total; p += 4) {
        const int kk = s_list[p];
        const float2* eqp = (const float2*)(e_qry + ((size_t)(b * SS + kk) * SS + q) * DD);
        const float2* ekp = (const float2*)(e_key + ((size_t)(b * SS + q) * SS + kk) * DD);
        const float2* kpp = (const float2*)(g_kp + (size_t)(b * SS + kk) * 256);
        float2 eq = eqp[lane];
        float2 ek = ekp[lane];
        float ps[4];
        #pragma unroll
        for (int h = 0; h < 4; h++) {
            float2 qv = *(const float2*)&s_q[h * 64 + lane * 2];
            float2 kv = kpp[h * 32 + lane];
            ps[h] = (qv.x + eq.x) * (kv.x + ek.x) + (qv.y + eq.y) * (kv.y + ek.y);
        }
        #pragma unroll
        for (int off = 16; off; off >>= 1)
            #pragma unroll
            for (int h = 0; h < 4; h++)
                ps[h] += __shfl_down_sync(0xFFFFFFFFu, ps[h], off);
        if (lane == 0)
            #pragma unroll
            for (int h = 0; h < 4; h++) s_sc[h][p] = ps[h] * SCALE;
    }
    __syncthreads();

    // ---- softmax over live set (warp w == head h) ----
    if (total > 0) {
        float m = -3.0e38f;
        for (int p = lane; p < total; p += 32) m = fmaxf(m, s_sc[w][p]);
        #pragma unroll
        for (int off = 16; off; off >>= 1)
            m = fmaxf(m, __shfl_xor_sync(0xFFFFFFFFu, m, off));
        float sum = 0.0f;
        for (int p = lane; p < total; p += 32) {
            float e = __expf(s_sc[w][p] - m);
            s_sc[w][p] = e;
            sum += e;
        }
        #pragma unroll
        for (int off = 16; off; off >>= 1)
            sum += __shfl_xor_sync(0xFFFFFFFFu, sum, off);
        float inv = 1.0f / sum;
        for (int p = lane; p < total; p += 32) s_sc[w][p] *= inv;
    }
    __syncthreads();

    // ---- output: thread t owns one float2 of the 256-wide row ----
    const int dp = t & 63;
    const int hp = t >> 6;               // 0 or 1
    const int h  = 2 * hp + (dp >> 5);
    const int dd = (dp * 2) & 63;
    float2 acc = make_float2(0.0f, 0.0f);
    const float* evbase = e_val + ((size_t)(b * SS + q) * SS) * DD;

    if (total > 0) {
        #pragma unroll 4
        for (int p = 0; p < total; p++) {
            const int kk = s_list[p];
            float2 ev = *(const float2*)&evbase[(size_t)kk * DD + dd];
            float2 vv = *(const float2*)&g_vp[(size_t)(b * SS + kk) * 256 + hp * 128 + dp * 2];
            float sc = s_sc[h][p];
            acc.x += sc * (vv.x + ev.x);
            acc.y += sc * (vv.y + ev.y);
        }
    } else {
        // all columns masked -> softmax of equal values -> uniform 1/S
        #pragma unroll 4
        for (int kk = 0; kk < SS; kk++) {
            float2 ev = *(const float2*)&evbase[(size_t)kk * DD + dd];
            float2 vv = *(const float2*)&g_vp[(size_t)(b * SS + kk) * 256 + hp * 128 + dp * 2];
            acc.x += vv.x + ev.x;
            acc.y += vv.y + ev.y;
        }
        const float invS = 1.0f / (float)SS;
        acc.x *= invS; acc.y *= invS;
    }
    *(float2*)&g_x[(size_t)row * 256 + hp * 128 + dp * 2] = acc;
}

// ---------------------------------------------------------------------------
extern "C" void kernel_launch(void* const* d_in, const int* in_sizes, int n_in,
                              void* d_out, int out_size)
{
    const float* query = (const float*)d_in[0];
    const float* key   = (const float*)d_in[1];
    const float* value = (const float*)d_in[2];
    const int*   graph = (const int*)  d_in[3];
    const float* e_key = (const float*)d_in[4];
    const float* e_val = (const float*)d_in[5];
    const float* e_qry = (const float*)d_in[6];
    const float* Wq = (const float*)d_in[7];
    const float* bq = (const float*)d_in[8];
    const float* Wk = (const float*)d_in[9];
    const float* bk = (const float*)d_in[10];
    const float* Wv = (const float*)d_in[11];
    const float* bv = (const float*)d_in[12];
    const float* Wo = (const float*)d_in[13];
    const float* bo = (const float*)d_in[14];
    float* out = (float*)d_out;

    dim3 g_qkv(M_ROWS / 32, 256 / 128, 3);
    gemm_qkv_kernel<<<g_qkv, 128>>>(query, key, value, Wq, Wk, Wv, bq, bk, bv);

    attn_kernel<<<M_ROWS, 128>>>(graph, e_key, e_val, e_qry);

    dim3 g_o(M_ROWS / 32, 256 / 128, 1);
    gemm_out_kernel<<<g_o, 128>>>(Wo, bo, out);
}